// round 3
// baseline (speedup 1.0000x reference)
#include <cuda_runtime.h>
#include <cuda_bf16.h>
#include <math.h>

#define DV 33
#define D2 (DV*DV)        // 1089
#define D3 (DV*DV*DV)     // 35937
#define NLUT (3*D3)       // 107811
#define B 4
#define NPIX (1024*1024)

// ---------------- scratch ----------------------------------------------------
__device__ float g_resized[B*3*256*256];
__device__ float g_x1[B*16*128*128];
__device__ float g_x2[B*32*64*64];
__device__ float g_x3[B*64*32*32];
__device__ float g_x4[B*128*16*16];
__device__ float g_codes[B*512];
// raw stats per (b,c): [sum,sumsq]: ss1@0(128) ss2@128(256) ss3@384(512) ss4@896(1024)
__device__ float g_stats[1920];
__device__ float g_wts[B*3];
__device__ float g_verts[B*3*DV];
__device__ float4 g_lut4[B*D3];

__global__ void zero_k(float* p, int n)
{
    int i = blockIdx.x*blockDim.x + threadIdx.x;
    if (i < n) p[i] = 0.f;
}

// ---------------- resize: 1024 -> 256, scale 4, half-pixel => avg 2x2 @(+1,+1)
__global__ void resize_k(const float* __restrict__ lq, float* __restrict__ out)
{
    int idx = blockIdx.x * blockDim.x + threadIdx.x;
    if (idx >= B*3*256*256) return;
    int ox = idx & 255;
    int oy = (idx >> 8) & 255;
    int bc = idx >> 16;
    const float* ip = lq + (size_t)bc * 1024 * 1024 + (size_t)(4*oy+1)*1024 + (4*ox+1);
    out[idx] = 0.25f * (ip[0] + ip[1] + ip[1024] + ip[1025]);
}

// ---------------- conv1 (IC=3): direct, branch-free predicated loads ---------
template<int IC, int OC, int OCB, int INHW, int OUTHW>
__global__ void conv1_k(const float* __restrict__ in, const float* __restrict__ w,
                        const float* __restrict__ bias,
                        float* __restrict__ stat_out, float* __restrict__ out)
{
    const int b = blockIdx.z;
    const int ocg = blockIdx.y;
    const int tid = threadIdx.x;
    __shared__ float sw[IC*9*OCB];
    for (int i = tid; i < IC*9*OCB; i += 256) {
        int o = i % OCB, t = i / OCB;
        int k = t % 9, ic = t / 9;
        sw[i] = w[((ocg*OCB + o)*IC + ic)*9 + k];
    }
    __syncthreads();

    int p = blockIdx.x*256 + tid;
    int oy = p / OUTHW, ox = p % OUTHW;
    float acc[OCB];
    #pragma unroll
    for (int o = 0; o < OCB; o++) acc[o] = bias[ocg*OCB+o];

    const float* inb = in + (size_t)b*IC*INHW*INHW + (2*oy-1)*INHW + (2*ox-1);
    const bool okT = (oy > 0);
    const bool okL = (ox > 0);

    #pragma unroll
    for (int ic = 0; ic < IC; ic++) {
        const float* ip = inb + (size_t)ic*INHW*INHW;
        float v[9];
        #pragma unroll
        for (int ky = 0; ky < 3; ky++)
            #pragma unroll
            for (int kx = 0; kx < 3; kx++) {
                bool ok = (okT || ky > 0) && (okL || kx > 0);
                v[ky*3+kx] = ok ? ip[ky*INHW+kx] : 0.f;
            }
        #pragma unroll
        for (int k = 0; k < 9; k++) {
            float t = v[k];
            #pragma unroll
            for (int o = 0; o < OCB; o++)
                acc[o] = fmaf(t, sw[(ic*9+k)*OCB+o], acc[o]);
        }
    }

    float ys[OCB];
    #pragma unroll
    for (int o = 0; o < OCB; o++) {
        float y = acc[o];
        y = y >= 0.f ? y : 0.2f*y;
        ys[o] = y;
        out[(((size_t)b*OC + ocg*OCB + o)*OUTHW)*OUTHW + p] = y;
    }

    float s1[OCB], s2[OCB];
    #pragma unroll
    for (int o = 0; o < OCB; o++) { s1[o] = ys[o]; s2[o] = ys[o]*ys[o]; }
    #pragma unroll
    for (int o = 0; o < OCB; o++)
        #pragma unroll
        for (int off = 16; off; off >>= 1) {
            s1[o] += __shfl_xor_sync(0xffffffffu, s1[o], off);
            s2[o] += __shfl_xor_sync(0xffffffffu, s2[o], off);
        }
    __shared__ float2 red[OCB][8];
    int warp = tid >> 5, lane = tid & 31;
    if (lane == 0)
        #pragma unroll
        for (int o = 0; o < OCB; o++) red[o][warp] = make_float2(s1[o], s2[o]);
    __syncthreads();
    if (tid < OCB) {
        float a = 0.f, c = 0.f;
        #pragma unroll
        for (int wdx = 0; wdx < 8; wdx++) { a += red[tid][wdx].x; c += red[tid][wdx].y; }
        int bc = b*OC + ocg*OCB + tid;
        atomicAdd(stat_out + bc*2, a);
        atomicAdd(stat_out + bc*2+1, c);
    }
}

// ---------------- smem-tiled conv: 16x16 out-tile, IC chunked ----------------
template<int IC, int OC, int OCB, int INHW, int OUTHW, int CHUNK>
__global__ void convt_k(const float* __restrict__ in, const float* __restrict__ w,
                        const float* __restrict__ bias,
                        const float* __restrict__ stat_in,
                        const float* __restrict__ gamma, const float* __restrict__ beta,
                        float* __restrict__ stat_out,
                        float* __restrict__ out)
{
    const int TILES_X = OUTHW/16;
    const int b = blockIdx.z;
    const int ocg = blockIdx.y;
    const int tile = blockIdx.x;
    const int tx0 = (tile % TILES_X)*16, ty0 = (tile / TILES_X)*16;
    const int tid = threadIdx.x;

    __shared__ float tileS[CHUNK][33*33];
    __shared__ float sw[CHUNK*9*OCB];
    __shared__ float ssc[IC], ssh[IC];

    for (int i = tid; i < IC; i += 256) {
        const float invn = 1.f / (float)(INHW*INHW);
        float s1 = stat_in[(b*IC+i)*2], s2 = stat_in[(b*IC+i)*2+1];
        float mean = s1 * invn;
        float var  = s2 * invn - mean*mean;
        float sc = gamma[i] * rsqrtf(var + 1e-5f);
        ssc[i] = sc;
        ssh[i] = beta[i] - mean * sc;
    }
    __syncthreads();

    float acc[OCB];
    #pragma unroll
    for (int o = 0; o < OCB; o++) acc[o] = bias[ocg*OCB+o];

    const int oy = tid >> 4, ox = tid & 15;

    for (int c0 = 0; c0 < IC; c0 += CHUNK) {
        // weights for this chunk
        for (int i = tid; i < CHUNK*9*OCB; i += 256) {
            int o = i % OCB, t = i / OCB;
            int k = t % 9, icl = t / 9;
            sw[i] = w[((ocg*OCB + o)*IC + c0 + icl)*9 + k];
        }
        // input tile (33x33 per ic), affine folded, zero padding
        #pragma unroll
        for (int icl = 0; icl < CHUNK; icl++) {
            const float* ip = in + ((size_t)b*IC + c0 + icl)*INHW*INHW;
            float s = ssc[c0+icl], sh = ssh[c0+icl];
            for (int e = tid; e < 33*33; e += 256) {
                int rr = e / 33, cc = e - rr*33;
                int gy = 2*ty0 - 1 + rr, gx = 2*tx0 - 1 + cc;
                bool ok = (gy >= 0) && (gx >= 0);
                float v = ok ? ip[gy*INHW + gx] : 0.f;
                tileS[icl][e] = ok ? fmaf(v, s, sh) : 0.f;
            }
        }
        __syncthreads();
        #pragma unroll
        for (int icl = 0; icl < CHUNK; icl++) {
            const float* tb = &tileS[icl][(2*oy)*33 + 2*ox];
            float v[9];
            #pragma unroll
            for (int ky = 0; ky < 3; ky++)
                #pragma unroll
                for (int kx = 0; kx < 3; kx++)
                    v[ky*3+kx] = tb[ky*33+kx];
            #pragma unroll
            for (int k = 0; k < 9; k++) {
                float t = v[k];
                #pragma unroll
                for (int o = 0; o < OCB; o++)
                    acc[o] = fmaf(t, sw[(icl*9+k)*OCB+o], acc[o]);
            }
        }
        __syncthreads();
    }

    float ys[OCB];
    #pragma unroll
    for (int o = 0; o < OCB; o++) {
        float y = acc[o];
        y = y >= 0.f ? y : 0.2f*y;
        ys[o] = y;
        out[(((size_t)b*OC + ocg*OCB + o)*OUTHW + ty0 + oy)*OUTHW + tx0 + ox] = y;
    }

    float s1[OCB], s2[OCB];
    #pragma unroll
    for (int o = 0; o < OCB; o++) { s1[o] = ys[o]; s2[o] = ys[o]*ys[o]; }
    #pragma unroll
    for (int o = 0; o < OCB; o++)
        #pragma unroll
        for (int off = 16; off; off >>= 1) {
            s1[o] += __shfl_xor_sync(0xffffffffu, s1[o], off);
            s2[o] += __shfl_xor_sync(0xffffffffu, s2[o], off);
        }
    __shared__ float2 red[OCB][8];
    int warp = tid >> 5, lane = tid & 31;
    if (lane == 0)
        #pragma unroll
        for (int o = 0; o < OCB; o++) red[o][warp] = make_float2(s1[o], s2[o]);
    __syncthreads();
    if (tid < OCB) {
        float a = 0.f, c = 0.f;
        #pragma unroll
        for (int wdx = 0; wdx < 8; wdx++) { a += red[tid][wdx].x; c += red[tid][wdx].y; }
        int bc = b*OC + ocg*OCB + tid;
        atomicAdd(stat_out + bc*2, a);
        atomicAdd(stat_out + bc*2+1, c);
    }
}

// ---------------- conv5 + LeakyReLU + adaptive-avgpool(2) -> codes -----------
// block = (ocg in [0,16), b); 256 threads = 64 px x 4 osub (2 oc each)
__global__ void conv5_pool_k(const float* __restrict__ in, const float* __restrict__ w,
                             const float* __restrict__ bias,
                             const float* __restrict__ stat_in,
                             const float* __restrict__ gamma, const float* __restrict__ beta,
                             float* __restrict__ codes)
{
    const int IC = 128, CHUNK = 32, OCPB = 8;   // 8 oc per block
    const int b = blockIdx.y, ocg = blockIdx.x;
    const int tid = threadIdx.x;
    const int px = tid & 63, osub = tid >> 6;   // osub in [0,4): oc pair
    const int oy = px >> 3, ox = px & 7;

    __shared__ float tileS[CHUNK][17*17];
    __shared__ float sw[CHUNK*9*OCPB];
    __shared__ float ssc[IC], ssh[IC];
    __shared__ float sred[OCPB][64];

    for (int i = tid; i < IC; i += 256) {
        const float invn = 1.f / 256.f;
        float s1 = stat_in[(b*IC+i)*2], s2 = stat_in[(b*IC+i)*2+1];
        float mean = s1 * invn;
        float var  = s2 * invn - mean*mean;
        float sc = gamma[i] * rsqrtf(var + 1e-5f);
        ssc[i] = sc;
        ssh[i] = beta[i] - mean * sc;
    }
    __syncthreads();

    float acc[2];
    acc[0] = bias[ocg*OCPB + osub*2];
    acc[1] = bias[ocg*OCPB + osub*2 + 1];

    for (int c0 = 0; c0 < IC; c0 += CHUNK) {
        for (int i = tid; i < CHUNK*9*OCPB; i += 256) {
            int o = i % OCPB, t = i / OCPB;
            int k = t % 9, icl = t / 9;
            sw[i] = w[((ocg*OCPB + o)*IC + c0 + icl)*9 + k];
        }
        for (int e = tid; e < CHUNK*289; e += 256) {
            int icl = e / 289, r = e - icl*289;
            int rr = r / 17, cc = r - rr*17;
            int gy = rr - 1, gx = cc - 1;
            bool ok = (gy >= 0) && (gx >= 0);
            const float* ip = in + ((size_t)b*IC + c0 + icl)*256;
            float v = ok ? ip[gy*16 + gx] : 0.f;
            tileS[icl][r] = ok ? fmaf(v, ssc[c0+icl], ssh[c0+icl]) : 0.f;
        }
        __syncthreads();
        #pragma unroll
        for (int icl = 0; icl < CHUNK; icl++) {
            const float* tb = &tileS[icl][(2*oy)*17 + 2*ox];
            float v[9];
            #pragma unroll
            for (int ky = 0; ky < 3; ky++)
                #pragma unroll
                for (int kx = 0; kx < 3; kx++)
                    v[ky*3+kx] = tb[ky*17+kx];
            #pragma unroll
            for (int k = 0; k < 9; k++) {
                float t = v[k];
                acc[0] = fmaf(t, sw[(icl*9+k)*OCPB + osub*2],     acc[0]);
                acc[1] = fmaf(t, sw[(icl*9+k)*OCPB + osub*2 + 1], acc[1]);
            }
        }
        __syncthreads();
    }

    sred[osub*2][px]   = acc[0] >= 0.f ? acc[0] : 0.2f*acc[0];
    sred[osub*2+1][px] = acc[1] >= 0.f ? acc[1] : 0.2f*acc[1];
    __syncthreads();
    if (tid < 32) {
        int o = tid >> 2, q = tid & 3, py = q >> 1, qx = q & 1;
        float s = 0.f;
        #pragma unroll
        for (int yy = 0; yy < 4; yy++)
            #pragma unroll
            for (int xx = 0; xx < 4; xx++)
                s += sred[o][(py*4+yy)*8 + (qx*4+xx)];
        codes[b*512 + (ocg*OCPB + o)*4 + q] = s * (1.f/16.f);
    }
}

// ---------------- LUT weights + AdaInt vertices ------------------------------
__global__ void mlp_k(const float* __restrict__ codes,
                      const float* __restrict__ lw, const float* __restrict__ lb,
                      const float* __restrict__ aw, const float* __restrict__ ab,
                      float* __restrict__ wts, float* __restrict__ verts,
                      float* __restrict__ out_w, float* __restrict__ out_v)
{
    int b = blockIdx.x;
    __shared__ float sc[512];
    __shared__ float pre[96];
    for (int i = threadIdx.x; i < 512; i += blockDim.x) sc[i] = codes[b*512 + i];
    __syncthreads();
    int t = threadIdx.x;
    if (t < 96) {
        float acc = ab[t];
        const float* ar = aw + t*512;
        for (int k = 0; k < 512; k++) acc = fmaf(sc[k], ar[k], acc);
        pre[t] = acc;
    } else if (t < 99) {
        int r = t - 96;
        float acc = lb[r];
        const float* lr = lw + r*512;
        for (int k = 0; k < 512; k++) acc = fmaf(sc[k], lr[k], acc);
        wts[b*3 + r] = acc;
        out_w[b*3 + r] = acc;
    }
    __syncthreads();
    int warp = t >> 5, lane = t & 31;
    if (warp < 3) {
        float x = pre[warp*32 + lane];
        float m = x;
        #pragma unroll
        for (int off = 16; off; off >>= 1) m = fmaxf(m, __shfl_xor_sync(0xffffffffu, m, off));
        float e = expf(x - m);
        float ssum = e;
        #pragma unroll
        for (int off = 16; off; off >>= 1) ssum += __shfl_xor_sync(0xffffffffu, ssum, off);
        float p = e / ssum;
        float cs = p;
        #pragma unroll
        for (int off = 1; off < 32; off <<= 1) {
            float v = __shfl_up_sync(0xffffffffu, cs, off);
            if (lane >= off) cs += v;
        }
        float* vp = verts + (b*3 + warp)*DV;
        float* vo = out_v + (b*3 + warp)*DV;
        if (lane == 0) { vp[0] = 0.f; vo[0] = 0.f; }
        vp[lane+1] = cs;
        vo[lane+1] = cs;
    }
}

// ---------------- lut synthesis into channel-interleaved float4 --------------
// lut4[b][i*D2+j*DV+k] = (Lr, Lg, Lb, 0)
__global__ void lut4_k(const float* __restrict__ bw, const float* __restrict__ wts,
                       float4* __restrict__ lut4)
{
    int i = blockIdx.x*blockDim.x + threadIdx.x;
    if (i >= B*D3) return;
    int b = i / D3, s = i - b*D3;
    float w0 = wts[b*3], w1 = wts[b*3+1], w2 = wts[b*3+2];
    float4 r;
    {
        const float* br = bw + (size_t)s*3;
        r.x = fmaf(w0, br[0], fmaf(w1, br[1], w2*br[2]));
    }
    {
        const float* br = bw + ((size_t)D3 + s)*3;
        r.y = fmaf(w0, br[0], fmaf(w1, br[1], w2*br[2]));
    }
    {
        const float* br = bw + ((size_t)2*D3 + s)*3;
        r.z = fmaf(w0, br[0], fmaf(w1, br[1], w2*br[2]));
    }
    r.w = 0.f;
    lut4[i] = r;
}

// ---------------- AiLUT transform: inv-table searchsorted + float4 trilerp ---
__global__ void transform_k(const float* __restrict__ lq, const float4* __restrict__ lut4,
                            const float* __restrict__ verts, float* __restrict__ out)
{
    int b = blockIdx.x >> 10;
    int blk = blockIdx.x & 1023;
    int tid = threadIdx.x;
    __shared__ float sv[3][DV];
    __shared__ int tbl[3][128];
    if (tid < 99) sv[tid/33][tid%33] = verts[b*99 + tid];
    __syncthreads();
    for (int t = tid; t < 384; t += 256) {
        int ch = t >> 7, e = t & 127;
        float edge = (float)e * (1.f/128.f);
        int idx = 0;
        #pragma unroll 8
        for (int m = 1; m <= 32; m++)
            if (sv[ch][m] <= edge) idx = m;
        tbl[ch][e] = idx;
    }
    __syncthreads();

    int n = (blk*256 + tid) * 4;
    const float* lqb = lq + (size_t)b*3*NPIX;
    float4 R  = *(const float4*)(lqb + n);
    float4 G  = *(const float4*)(lqb + NPIX + n);
    float4 Bl = *(const float4*)(lqb + 2*NPIX + n);

    float xr[4] = {R.x, R.y, R.z, R.w};
    float xg[4] = {G.x, G.y, G.z, G.w};
    float xb[4] = {Bl.x, Bl.y, Bl.z, Bl.w};
    float orr[4], org[4], orb[4];

    const float4* base = lut4 + (size_t)b*D3;

    #pragma unroll
    for (int px = 0; px < 4; px++) {
        float crd[3];
        float xs[3] = {xr[px], xg[px], xb[px]};
        #pragma unroll
        for (int ch = 0; ch < 3; ch++) {
            float x = xs[ch];
            int e = min((int)(x * 128.f), 127);
            int idx = tbl[ch][e];
            while (idx < 32 && sv[ch][idx+1] <= x) idx++;
            int lo = min(idx, 31);
            float vl = sv[ch][lo], vh = sv[ch][lo+1];
            float fr = (x - vl) / (vh - vl + 1e-8f);
            float cd = (float)lo + fr;
            crd[ch] = fminf(fmaxf(cd, 0.f), 32.f);
        }
        int i0 = min((int)crd[0], 31);
        int j0 = min((int)crd[1], 31);
        int k0 = min((int)crd[2], 31);
        float fr = crd[0] - (float)i0;
        float fg = crd[1] - (float)j0;
        float fb = crd[2] - (float)k0;

        const float4* p = base + i0*D2 + j0*DV + k0;
        float4 a00 = p[0],      b00 = p[1];
        float4 a01 = p[DV],     b01 = p[DV+1];
        float4 a10 = p[D2],     b10 = p[D2+1];
        float4 a11 = p[D2+DV],  b11 = p[D2+DV+1];

        float l00x = fmaf(fb, b00.x - a00.x, a00.x);
        float l00y = fmaf(fb, b00.y - a00.y, a00.y);
        float l00z = fmaf(fb, b00.z - a00.z, a00.z);
        float l01x = fmaf(fb, b01.x - a01.x, a01.x);
        float l01y = fmaf(fb, b01.y - a01.y, a01.y);
        float l01z = fmaf(fb, b01.z - a01.z, a01.z);
        float l10x = fmaf(fb, b10.x - a10.x, a10.x);
        float l10y = fmaf(fb, b10.y - a10.y, a10.y);
        float l10z = fmaf(fb, b10.z - a10.z, a10.z);
        float l11x = fmaf(fb, b11.x - a11.x, a11.x);
        float l11y = fmaf(fb, b11.y - a11.y, a11.y);
        float l11z = fmaf(fb, b11.z - a11.z, a11.z);

        float h0x = fmaf(fg, l01x - l00x, l00x);
        float h0y = fmaf(fg, l01y - l00y, l00y);
        float h0z = fmaf(fg, l01z - l00z, l00z);
        float h1x = fmaf(fg, l11x - l10x, l10x);
        float h1y = fmaf(fg, l11y - l10y, l10y);
        float h1z = fmaf(fg, l11z - l10z, l10z);

        orr[px] = fminf(fmaxf(fmaf(fr, h1x - h0x, h0x), 0.f), 1.f);
        org[px] = fminf(fmaxf(fmaf(fr, h1y - h0y, h0y), 0.f), 1.f);
        orb[px] = fminf(fmaxf(fmaf(fr, h1z - h0z, h0z), 0.f), 1.f);
    }

    float* ob = out + (size_t)b*3*NPIX + n;
    *(float4*)(ob)          = make_float4(orr[0], orr[1], orr[2], orr[3]);
    *(float4*)(ob + NPIX)   = make_float4(org[0], org[1], org[2], org[3]);
    *(float4*)(ob + 2*NPIX) = make_float4(orb[0], orb[1], orb[2], orb[3]);
}

// ---------------- host launcher ----------------------------------------------
extern "C" void kernel_launch(void* const* d_in, const int* in_sizes, int n_in,
                              void* d_out, int out_size)
{
    const float* lq  = (const float*)d_in[0];
    const float* w1  = (const float*)d_in[1];
    const float* b1  = (const float*)d_in[2];
    const float* g1  = (const float*)d_in[3];
    const float* be1 = (const float*)d_in[4];
    const float* w2  = (const float*)d_in[5];
    const float* b2  = (const float*)d_in[6];
    const float* g2  = (const float*)d_in[7];
    const float* be2 = (const float*)d_in[8];
    const float* w3  = (const float*)d_in[9];
    const float* b3  = (const float*)d_in[10];
    const float* g3  = (const float*)d_in[11];
    const float* be3 = (const float*)d_in[12];
    const float* w4  = (const float*)d_in[13];
    const float* b4  = (const float*)d_in[14];
    const float* g4  = (const float*)d_in[15];
    const float* be4 = (const float*)d_in[16];
    const float* w5  = (const float*)d_in[17];
    const float* b5  = (const float*)d_in[18];
    const float* lw  = (const float*)d_in[19];
    const float* lb  = (const float*)d_in[20];
    const float* bw  = (const float*)d_in[21];
    const float* aw  = (const float*)d_in[22];
    const float* ab  = (const float*)d_in[23];

    float *res, *x1, *x2, *x3, *x4, *codes, *stats, *wts, *verts;
    float4* lut4;
    cudaGetSymbolAddress((void**)&res,   g_resized);
    cudaGetSymbolAddress((void**)&x1,    g_x1);
    cudaGetSymbolAddress((void**)&x2,    g_x2);
    cudaGetSymbolAddress((void**)&x3,    g_x3);
    cudaGetSymbolAddress((void**)&x4,    g_x4);
    cudaGetSymbolAddress((void**)&codes, g_codes);
    cudaGetSymbolAddress((void**)&stats, g_stats);
    cudaGetSymbolAddress((void**)&wts,   g_wts);
    cudaGetSymbolAddress((void**)&verts, g_verts);
    cudaGetSymbolAddress((void**)&lut4,  g_lut4);

    float* ss1 = stats;          // 4*16*2  = 128
    float* ss2 = stats + 128;    // 4*32*2  = 256
    float* ss3 = stats + 384;    // 4*64*2  = 512
    float* ss4 = stats + 896;    // 4*128*2 = 1024

    float* out = (float*)d_out;
    const int OFF_W = B*3*NPIX;
    const int OFF_V = OFF_W + B*3;

    zero_k<<<8, 256>>>(stats, 1920);

    resize_k<<<(B*3*256*256 + 255)/256, 256>>>(lq, res);

    conv1_k<3, 16, 8, 256, 128><<<dim3(64, 2, B), 256>>>(res, w1, b1, ss1, x1);

    convt_k<16, 32, 8, 128, 64, 8><<<dim3(16, 4, B), 256>>>(
        x1, w2, b2, ss1, g1, be1, ss2, x2);

    convt_k<32, 64, 8, 64, 32, 8><<<dim3(4, 8, B), 256>>>(
        x2, w3, b3, ss2, g2, be2, ss3, x3);

    convt_k<64, 128, 4, 32, 16, 8><<<dim3(1, 32, B), 256>>>(
        x3, w4, b4, ss3, g3, be3, ss4, x4);

    conv5_pool_k<<<dim3(16, B), 256>>>(x4, w5, b5, ss4, g4, be4, codes);

    mlp_k<<<B, 128>>>(codes, lw, lb, aw, ab, wts, verts, out + OFF_W, out + OFF_V);

    lut4_k<<<(B*D3 + 255)/256, 256>>>(bw, wts, lut4);

    transform_k<<<B*1024, 256>>>(lq, lut4, verts, out);
}

// round 4
// speedup vs baseline: 1.4739x; 1.4739x over previous
#include <cuda_runtime.h>
#include <cuda_bf16.h>
#include <math.h>

#define DV 33
#define D2 (DV*DV)        // 1089
#define D3 (DV*DV*DV)     // 35937
#define B 4
#define NPIX (1024*1024)

// ---------------- scratch ----------------------------------------------------
__device__ float g_resized[B*3*256*256];
__device__ float g_x1[B*16*128*128];
__device__ float g_x2[B*32*64*64];
__device__ float g_x3[B*64*32*32];
__device__ float g_x4[B*128*16*16];
__device__ float g_codes[B*512];
// raw stats per (b,c): [sum,sumsq]: ss1@0(128) ss2@128(256) ss3@384(512) ss4@896(1024)
__device__ float g_stats[1920];
__device__ float g_wts[B*3];
__device__ float g_verts[B*3*DV];
__device__ float4 g_lut4[B*D3];

__global__ void zero_k(float* p, int n)
{
    int i = blockIdx.x*blockDim.x + threadIdx.x;
    if (i < n) p[i] = 0.f;
}

// ---------------- resize: 1024 -> 256, scale 4, half-pixel => avg 2x2 @(+1,+1)
__global__ void resize_k(const float* __restrict__ lq, float* __restrict__ out)
{
    int idx = blockIdx.x * blockDim.x + threadIdx.x;
    if (idx >= B*3*256*256) return;
    int ox = idx & 255;
    int oy = (idx >> 8) & 255;
    int bc = idx >> 16;
    const float* ip = lq + (size_t)bc * 1024 * 1024 + (size_t)(4*oy+1)*1024 + (4*ox+1);
    out[idx] = 0.25f * (ip[0] + ip[1] + ip[1024] + ip[1025]);
}

// ---------------- direct conv: k3 s2 p1 + LeakyReLU; IN folded; fused stats --
template<int IC, int OC, int OCB, int INHW, int OUTHW, bool HAS_IN>
__global__ void __launch_bounds__(256) conv_k(
                       const float* __restrict__ in, const float* __restrict__ w,
                       const float* __restrict__ bias,
                       const float* __restrict__ stat_in,
                       const float* __restrict__ gamma, const float* __restrict__ beta,
                       float* __restrict__ stat_out,
                       float* __restrict__ out)
{
    const int b = blockIdx.z;
    const int ocg = blockIdx.y;
    const int tid = threadIdx.x;
    __shared__ float sw[IC*9*OCB];
    __shared__ float ssc[IC];
    __shared__ float ssh[IC];
    for (int i = tid; i < IC*9*OCB; i += 256) {
        int o = i % OCB, t = i / OCB;
        int k = t % 9, ic = t / 9;
        sw[i] = w[((ocg*OCB + o)*IC + ic)*9 + k];
    }
    if (HAS_IN) {
        for (int i = tid; i < IC; i += 256) {
            const float invn = 1.f / (float)(INHW*INHW);
            float s1 = stat_in[(b*IC+i)*2], s2 = stat_in[(b*IC+i)*2+1];
            float mean = s1 * invn;
            float var  = s2 * invn - mean*mean;
            float sc = gamma[i] * rsqrtf(var + 1e-5f);
            ssc[i] = sc;
            ssh[i] = beta[i] - mean * sc;
        }
    }
    __syncthreads();

    int p = blockIdx.x*256 + tid;         // OUTHW*OUTHW multiple of 256
    int oy = p / OUTHW, ox = p % OUTHW;
    float acc[OCB];
    #pragma unroll
    for (int o = 0; o < OCB; o++) acc[o] = bias[ocg*OCB+o];

    const float* inb = in + (size_t)b*IC*INHW*INHW + (2*oy-1)*INHW + (2*ox-1);
    const bool okT = (oy > 0);
    const bool okL = (ox > 0);

    for (int ic = 0; ic < IC; ic++) {
        const float* ip = inb + (size_t)ic*INHW*INHW;
        float v[9];
        #pragma unroll
        for (int ky = 0; ky < 3; ky++) {
            #pragma unroll
            for (int kx = 0; kx < 3; kx++) {
                bool ok = (okT || ky > 0) && (okL || kx > 0);
                v[ky*3+kx] = ok ? ip[ky*INHW+kx] : 0.f;
            }
        }
        if (HAS_IN) {
            float s = ssc[ic], sh = ssh[ic];
            #pragma unroll
            for (int ky = 0; ky < 3; ky++)
                #pragma unroll
                for (int kx = 0; kx < 3; kx++) {
                    bool ok = (okT || ky > 0) && (okL || kx > 0);
                    v[ky*3+kx] = ok ? fmaf(v[ky*3+kx], s, sh) : 0.f;
                }
        }
        #pragma unroll
        for (int k = 0; k < 9; k++) {
            float t = v[k];
            #pragma unroll
            for (int o = 0; o < OCB; o++)
                acc[o] = fmaf(t, sw[(ic*9+k)*OCB+o], acc[o]);
        }
    }

    float ys[OCB];
    #pragma unroll
    for (int o = 0; o < OCB; o++) {
        float y = acc[o];
        y = y >= 0.f ? y : 0.2f*y;
        ys[o] = y;
        out[(((size_t)b*OC + ocg*OCB + o)*OUTHW)*OUTHW + p] = y;
    }

    // fused stats: block-reduce sum/sumsq per oc, one atomic pair per block
    float s1[OCB], s2[OCB];
    #pragma unroll
    for (int o = 0; o < OCB; o++) { s1[o] = ys[o]; s2[o] = ys[o]*ys[o]; }
    #pragma unroll
    for (int o = 0; o < OCB; o++) {
        #pragma unroll
        for (int off = 16; off; off >>= 1) {
            s1[o] += __shfl_xor_sync(0xffffffffu, s1[o], off);
            s2[o] += __shfl_xor_sync(0xffffffffu, s2[o], off);
        }
    }
    __shared__ float2 red[OCB][8];
    int warp = tid >> 5, lane = tid & 31;
    if (lane == 0) {
        #pragma unroll
        for (int o = 0; o < OCB; o++) red[o][warp] = make_float2(s1[o], s2[o]);
    }
    __syncthreads();
    if (tid < OCB) {
        float a = 0.f, c = 0.f;
        #pragma unroll
        for (int wdx = 0; wdx < 8; wdx++) { a += red[tid][wdx].x; c += red[tid][wdx].y; }
        int bc = b*OC + ocg*OCB + tid;
        atomicAdd(stat_out + bc*2, a);
        atomicAdd(stat_out + bc*2+1, c);
    }
}

// ---------------- conv5 + LeakyReLU + adaptive-avgpool(2) -> codes -----------
// block = (ocg in [0,16), b); 256 threads = 64 px x 4 osub (2 oc each)
__global__ void __launch_bounds__(256) conv5_pool_k(
                             const float* __restrict__ in, const float* __restrict__ w,
                             const float* __restrict__ bias,
                             const float* __restrict__ stat_in,
                             const float* __restrict__ gamma, const float* __restrict__ beta,
                             float* __restrict__ codes)
{
    const int IC = 128, OCPB = 8;
    const int b = blockIdx.y, ocg = blockIdx.x;
    const int tid = threadIdx.x;
    const int px = tid & 63, osub = tid >> 6;
    const int oy = px >> 3, ox = px & 7;

    __shared__ float sw[IC*9*OCPB];
    __shared__ float ssc[IC], ssh[IC];
    __shared__ float sred[OCPB][64];

    for (int i = tid; i < IC; i += 256) {
        const float invn = 1.f / 256.f;
        float s1 = stat_in[(b*IC+i)*2], s2 = stat_in[(b*IC+i)*2+1];
        float mean = s1 * invn;
        float var  = s2 * invn - mean*mean;
        float sc = gamma[i] * rsqrtf(var + 1e-5f);
        ssc[i] = sc;
        ssh[i] = beta[i] - mean * sc;
    }
    for (int i = tid; i < IC*9*OCPB; i += 256) {
        int o = i % OCPB, t = i / OCPB;
        int k = t % 9, ic = t / 9;
        sw[i] = w[((ocg*OCPB + o)*IC + ic)*9 + k];
    }
    __syncthreads();

    float acc0 = bias[ocg*OCPB + osub*2];
    float acc1 = bias[ocg*OCPB + osub*2 + 1];

    const float* inb = in + (size_t)b*IC*256 + (2*oy-1)*16 + (2*ox-1);
    const bool okT = (oy > 0), okL = (ox > 0);

    for (int ic = 0; ic < IC; ic++) {
        const float* ip = inb + ic*256;
        float s = ssc[ic], sh = ssh[ic];
        float v[9];
        #pragma unroll
        for (int ky = 0; ky < 3; ky++)
            #pragma unroll
            for (int kx = 0; kx < 3; kx++) {
                bool ok = (okT || ky > 0) && (okL || kx > 0);
                float u = ok ? ip[ky*16+kx] : 0.f;
                v[ky*3+kx] = ok ? fmaf(u, s, sh) : 0.f;
            }
        #pragma unroll
        for (int k = 0; k < 9; k++) {
            float t = v[k];
            acc0 = fmaf(t, sw[(ic*9+k)*OCPB + osub*2],     acc0);
            acc1 = fmaf(t, sw[(ic*9+k)*OCPB + osub*2 + 1], acc1);
        }
    }

    sred[osub*2][px]   = acc0 >= 0.f ? acc0 : 0.2f*acc0;
    sred[osub*2+1][px] = acc1 >= 0.f ? acc1 : 0.2f*acc1;
    __syncthreads();
    if (tid < 32) {
        int o = tid >> 2, q = tid & 3, py = q >> 1, qx = q & 1;
        float s = 0.f;
        #pragma unroll
        for (int yy = 0; yy < 4; yy++)
            #pragma unroll
            for (int xx = 0; xx < 4; xx++)
                s += sred[o][(py*4+yy)*8 + (qx*4+xx)];
        codes[b*512 + (ocg*OCPB + o)*4 + q] = s * (1.f/16.f);
    }
}

// ---------------- LUT weights + AdaInt vertices ------------------------------
__global__ void mlp_k(const float* __restrict__ codes,
                      const float* __restrict__ lw, const float* __restrict__ lb,
                      const float* __restrict__ aw, const float* __restrict__ ab,
                      float* __restrict__ wts, float* __restrict__ verts,
                      float* __restrict__ out_w, float* __restrict__ out_v)
{
    int b = blockIdx.x;
    __shared__ float sc[512];
    __shared__ float pre[96];
    for (int i = threadIdx.x; i < 512; i += blockDim.x) sc[i] = codes[b*512 + i];
    __syncthreads();
    int t = threadIdx.x;
    if (t < 96) {
        float acc = ab[t];
        const float* ar = aw + t*512;
        for (int k = 0; k < 512; k++) acc = fmaf(sc[k], ar[k], acc);
        pre[t] = acc;
    } else if (t < 99) {
        int r = t - 96;
        float acc = lb[r];
        const float* lr = lw + r*512;
        for (int k = 0; k < 512; k++) acc = fmaf(sc[k], lr[k], acc);
        wts[b*3 + r] = acc;
        out_w[b*3 + r] = acc;
    }
    __syncthreads();
    int warp = t >> 5, lane = t & 31;
    if (warp < 3) {
        float x = pre[warp*32 + lane];
        float m = x;
        #pragma unroll
        for (int off = 16; off; off >>= 1) m = fmaxf(m, __shfl_xor_sync(0xffffffffu, m, off));
        float e = expf(x - m);
        float ssum = e;
        #pragma unroll
        for (int off = 16; off; off >>= 1) ssum += __shfl_xor_sync(0xffffffffu, ssum, off);
        float p = e / ssum;
        float cs = p;
        #pragma unroll
        for (int off = 1; off < 32; off <<= 1) {
            float v = __shfl_up_sync(0xffffffffu, cs, off);
            if (lane >= off) cs += v;
        }
        float* vp = verts + (b*3 + warp)*DV;
        float* vo = out_v + (b*3 + warp)*DV;
        if (lane == 0) { vp[0] = 0.f; vo[0] = 0.f; }
        vp[lane+1] = cs;
        vo[lane+1] = cs;
    }
}

// ---------------- lut synthesis into channel-interleaved float4 --------------
__global__ void lut4_k(const float* __restrict__ bw, const float* __restrict__ wts,
                       float4* __restrict__ lut4)
{
    int i = blockIdx.x*blockDim.x + threadIdx.x;
    if (i >= B*D3) return;
    int b = i / D3, s = i - b*D3;
    float w0 = wts[b*3], w1 = wts[b*3+1], w2 = wts[b*3+2];
    float4 r;
    {
        const float* br = bw + (size_t)s*3;
        r.x = fmaf(w0, br[0], fmaf(w1, br[1], w2*br[2]));
    }
    {
        const float* br = bw + ((size_t)D3 + s)*3;
        r.y = fmaf(w0, br[0], fmaf(w1, br[1], w2*br[2]));
    }
    {
        const float* br = bw + ((size_t)2*D3 + s)*3;
        r.z = fmaf(w0, br[0], fmaf(w1, br[1], w2*br[2]));
    }
    r.w = 0.f;
    lut4[i] = r;
}

// ---------------- AiLUT transform: inv-table searchsorted + float4 trilerp ---
__global__ void __launch_bounds__(256) transform_k(
                            const float* __restrict__ lq, const float4* __restrict__ lut4,
                            const float* __restrict__ verts, float* __restrict__ out)
{
    int b = blockIdx.x >> 10;
    int blk = blockIdx.x & 1023;
    int tid = threadIdx.x;
    __shared__ float sv[3][DV];
    __shared__ int tbl[3][128];
    if (tid < 99) sv[tid/33][tid%33] = verts[b*99 + tid];
    __syncthreads();
    for (int t = tid; t < 384; t += 256) {
        int ch = t >> 7, e = t & 127;
        float edge = (float)e * (1.f/128.f);
        int idx = 0;
        #pragma unroll 8
        for (int m = 1; m <= 32; m++)
            if (sv[ch][m] <= edge) idx = m;
        tbl[ch][e] = idx;
    }
    __syncthreads();

    int n = (blk*256 + tid) * 4;
    const float* lqb = lq + (size_t)b*3*NPIX;
    float4 R  = *(const float4*)(lqb + n);
    float4 G  = *(const float4*)(lqb + NPIX + n);
    float4 Bl = *(const float4*)(lqb + 2*NPIX + n);

    float xr[4] = {R.x, R.y, R.z, R.w};
    float xg[4] = {G.x, G.y, G.z, G.w};
    float xb[4] = {Bl.x, Bl.y, Bl.z, Bl.w};
    float orr[4], org[4], orb[4];

    const float4* base = lut4 + (size_t)b*D3;

    #pragma unroll
    for (int px = 0; px < 4; px++) {
        float crd[3];
        float xs[3] = {xr[px], xg[px], xb[px]};
        #pragma unroll
        for (int ch = 0; ch < 3; ch++) {
            float x = xs[ch];
            int e = min((int)(x * 128.f), 127);
            int idx = tbl[ch][e];
            while (idx < 32 && sv[ch][idx+1] <= x) idx++;
            int lo = min(idx, 31);
            float vl = sv[ch][lo], vh = sv[ch][lo+1];
            float fr = (x - vl) / (vh - vl + 1e-8f);
            float cd = (float)lo + fr;
            crd[ch] = fminf(fmaxf(cd, 0.f), 32.f);
        }
        int i0 = min((int)crd[0], 31);
        int j0 = min((int)crd[1], 31);
        int k0 = min((int)crd[2], 31);
        float fr = crd[0] - (float)i0;
        float fg = crd[1] - (float)j0;
        float fb = crd[2] - (float)k0;

        const float4* p = base + i0*D2 + j0*DV + k0;
        float4 a00 = p[0],      b00 = p[1];
        float4 a01 = p[DV],     b01 = p[DV+1];
        float4 a10 = p[D2],     b10 = p[D2+1];
        float4 a11 = p[D2+DV],  b11 = p[D2+DV+1];

        float l00x = fmaf(fb, b00.x - a00.x, a00.x);
        float l00y = fmaf(fb, b00.y - a00.y, a00.y);
        float l00z = fmaf(fb, b00.z - a00.z, a00.z);
        float l01x = fmaf(fb, b01.x - a01.x, a01.x);
        float l01y = fmaf(fb, b01.y - a01.y, a01.y);
        float l01z = fmaf(fb, b01.z - a01.z, a01.z);
        float l10x = fmaf(fb, b10.x - a10.x, a10.x);
        float l10y = fmaf(fb, b10.y - a10.y, a10.y);
        float l10z = fmaf(fb, b10.z - a10.z, a10.z);
        float l11x = fmaf(fb, b11.x - a11.x, a11.x);
        float l11y = fmaf(fb, b11.y - a11.y, a11.y);
        float l11z = fmaf(fb, b11.z - a11.z, a11.z);

        float h0x = fmaf(fg, l01x - l00x, l00x);
        float h0y = fmaf(fg, l01y - l00y, l00y);
        float h0z = fmaf(fg, l01z - l00z, l00z);
        float h1x = fmaf(fg, l11x - l10x, l10x);
        float h1y = fmaf(fg, l11y - l10y, l10y);
        float h1z = fmaf(fg, l11z - l10z, l10z);

        orr[px] = fminf(fmaxf(fmaf(fr, h1x - h0x, h0x), 0.f), 1.f);
        org[px] = fminf(fmaxf(fmaf(fr, h1y - h0y, h0y), 0.f), 1.f);
        orb[px] = fminf(fmaxf(fmaf(fr, h1z - h0z, h0z), 0.f), 1.f);
    }

    float* ob = out + (size_t)b*3*NPIX + n;
    *(float4*)(ob)          = make_float4(orr[0], orr[1], orr[2], orr[3]);
    *(float4*)(ob + NPIX)   = make_float4(org[0], org[1], org[2], org[3]);
    *(float4*)(ob + 2*NPIX) = make_float4(orb[0], orb[1], orb[2], orb[3]);
}

// ---------------- host launcher ----------------------------------------------
extern "C" void kernel_launch(void* const* d_in, const int* in_sizes, int n_in,
                              void* d_out, int out_size)
{
    const float* lq  = (const float*)d_in[0];
    const float* w1  = (const float*)d_in[1];
    const float* b1  = (const float*)d_in[2];
    const float* g1  = (const float*)d_in[3];
    const float* be1 = (const float*)d_in[4];
    const float* w2  = (const float*)d_in[5];
    const float* b2  = (const float*)d_in[6];
    const float* g2  = (const float*)d_in[7];
    const float* be2 = (const float*)d_in[8];
    const float* w3  = (const float*)d_in[9];
    const float* b3  = (const float*)d_in[10];
    const float* g3  = (const float*)d_in[11];
    const float* be3 = (const float*)d_in[12];
    const float* w4  = (const float*)d_in[13];
    const float* b4  = (const float*)d_in[14];
    const float* g4  = (const float*)d_in[15];
    const float* be4 = (const float*)d_in[16];
    const float* w5  = (const float*)d_in[17];
    const float* b5  = (const float*)d_in[18];
    const float* lw  = (const float*)d_in[19];
    const float* lb  = (const float*)d_in[20];
    const float* bw  = (const float*)d_in[21];
    const float* aw  = (const float*)d_in[22];
    const float* ab  = (const float*)d_in[23];

    float *res, *x1, *x2, *x3, *x4, *codes, *stats, *wts, *verts;
    float4* lut4;
    cudaGetSymbolAddress((void**)&res,   g_resized);
    cudaGetSymbolAddress((void**)&x1,    g_x1);
    cudaGetSymbolAddress((void**)&x2,    g_x2);
    cudaGetSymbolAddress((void**)&x3,    g_x3);
    cudaGetSymbolAddress((void**)&x4,    g_x4);
    cudaGetSymbolAddress((void**)&codes, g_codes);
    cudaGetSymbolAddress((void**)&stats, g_stats);
    cudaGetSymbolAddress((void**)&wts,   g_wts);
    cudaGetSymbolAddress((void**)&verts, g_verts);
    cudaGetSymbolAddress((void**)&lut4,  g_lut4);

    float* ss1 = stats;          // 4*16*2  = 128
    float* ss2 = stats + 128;    // 4*32*2  = 256
    float* ss3 = stats + 384;    // 4*64*2  = 512
    float* ss4 = stats + 896;    // 4*128*2 = 1024

    float* out = (float*)d_out;
    const int OFF_W = B*3*NPIX;
    const int OFF_V = OFF_W + B*3;

    zero_k<<<8, 256>>>(stats, 1920);

    resize_k<<<(B*3*256*256 + 255)/256, 256>>>(lq, res);

    conv_k<3, 16, 8, 256, 128, false><<<dim3(64, 2, B), 256>>>(
        res, w1, b1, nullptr, nullptr, nullptr, ss1, x1);

    conv_k<16, 32, 4, 128, 64, true><<<dim3(16, 8, B), 256>>>(
        x1, w2, b2, ss1, g1, be1, ss2, x2);

    conv_k<32, 64, 4, 64, 32, true><<<dim3(4, 16, B), 256>>>(
        x2, w3, b3, ss2, g2, be2, ss3, x3);

    conv_k<64, 128, 4, 32, 16, true><<<dim3(1, 32, B), 256>>>(
        x3, w4, b4, ss3, g3, be3, ss4, x4);

    conv5_pool_k<<<dim3(16, B), 256>>>(x4, w5, b5, ss4, g4, be4, codes);

    mlp_k<<<B, 128>>>(codes, lw, lb, aw, ab, wts, verts, out + OFF_W, out + OFF_V);

    lut4_k<<<(B*D3 + 255)/256, 256>>>(bw, wts, lut4);

    transform_k<<<B*1024, 256>>>(lq, lut4, verts, out);
}

// round 7
// speedup vs baseline: 1.7337x; 1.1763x over previous
#include <cuda_runtime.h>
#include <cuda_bf16.h>
#include <cuda_fp16.h>
#include <math.h>

#define DV 33
#define D2 (DV*DV)        // 1089
#define D3 (DV*DV*DV)     // 35937
#define B 4
#define NPIX (1024*1024)

// ---------------- scratch ----------------------------------------------------
// feature maps stored DE-INTERLEAVED: per (b,c) plane of HW*HW floats is split
// into even columns [0, HW*HW/2) then odd columns [HW*HW/2, HW*HW)
__device__ float g_resized[B*3*256*256];
__device__ float g_x1[B*16*128*128];
__device__ float g_x2[B*32*64*64];
__device__ float g_x3[B*64*32*32];
__device__ float g_x4[B*128*16*16];
__device__ float g_codes[B*512];
// raw stats per (b,c): [sum,sumsq]: ss1@0(128) ss2@128(256) ss3@384(512) ss4@896(1024)
__device__ float g_stats[1920];
__device__ float g_wts[B*3];
__device__ float g_verts[B*3*DV];
__device__ uint4 g_lutH[B*D3];   // fp16 packed: (r0,g0,b0,r1,g1,b1,-,-) for (k,k+1)

__global__ void zero_k(float* p, int n)
{
    int i = blockIdx.x*blockDim.x + threadIdx.x;
    if (i < n) p[i] = 0.f;
}

// ---------------- resize: 1024->256 (avg 2x2 @(+1,+1)), write de-interleaved --
__global__ void resize_k(const float* __restrict__ lq, float* __restrict__ out)
{
    int idx = blockIdx.x * blockDim.x + threadIdx.x;
    if (idx >= B*3*256*256) return;
    int ox = idx & 255;
    int oy = (idx >> 8) & 255;
    int bc = idx >> 16;
    const float* ip = lq + (size_t)bc * 1024 * 1024 + (size_t)(4*oy+1)*1024 + (4*ox+1);
    float v = 0.25f * (ip[0] + ip[1] + ip[1024] + ip[1025]);
    out[(size_t)bc*65536 + (ox & 1)*32768 + oy*128 + (ox >> 1)] = v;
}

// ---------------- direct conv: k3 s2 p1 + LeakyReLU; de-interleaved I/O ------
// input de-interleaved (even plane, odd plane). taps for output col ox:
//   kx=0 -> odd[ox-1], kx=1 -> even[ox], kx=2 -> odd[ox]
template<int IC, int OC, int OCB, int INHW, int OUTHW, bool HAS_IN>
__global__ void __launch_bounds__(256) conv_k(
                       const float* __restrict__ in, const float* __restrict__ w,
                       const float* __restrict__ bias,
                       const float* __restrict__ stat_in,
                       const float* __restrict__ gamma, const float* __restrict__ beta,
                       float* __restrict__ stat_out,
                       float* __restrict__ out)
{
    const int HW2 = INHW/2;
    const int HALF = INHW*INHW/2;
    const int OHALF = OUTHW*OUTHW/2;
    const int b = blockIdx.z;
    const int ocg = blockIdx.y;
    const int tid = threadIdx.x;
    __shared__ float sw[IC*9*OCB];
    __shared__ float ssc[IC];
    __shared__ float ssh[IC];
    for (int i = tid; i < IC*9*OCB; i += 256) {
        int o = i % OCB, t = i / OCB;
        int k = t % 9, ic = t / 9;
        sw[i] = w[((ocg*OCB + o)*IC + ic)*9 + k];
    }
    if (HAS_IN) {
        for (int i = tid; i < IC; i += 256) {
            const float invn = 1.f / (float)(INHW*INHW);
            float s1 = stat_in[(b*IC+i)*2], s2 = stat_in[(b*IC+i)*2+1];
            float mean = s1 * invn;
            float var  = s2 * invn - mean*mean;
            float sc = gamma[i] * rsqrtf(var + 1e-5f);
            ssc[i] = sc;
            ssh[i] = beta[i] - mean * sc;
        }
    }
    __syncthreads();

    int p = blockIdx.x*256 + tid;         // OUTHW*OUTHW multiple of 256
    int oy = p / OUTHW, ox = p % OUTHW;
    float acc[OCB];
    #pragma unroll
    for (int o = 0; o < OCB; o++) acc[o] = bias[ocg*OCB+o];

    const bool okT = (oy > 0);
    const bool okL = (ox > 0);
    const float* inb = in + (size_t)b*IC*INHW*INHW + (2*oy-1)*HW2 + ox;

    for (int ic = 0; ic < IC; ic++) {
        const float* ipE = inb + (size_t)ic*INHW*INHW;
        const float* ipO = ipE + HALF;
        float v[9];
        #pragma unroll
        for (int ky = 0; ky < 3; ky++) {
            bool okR = (okT || ky > 0);
            int off = ky*HW2;
            v[ky*3+0] = (okR && okL) ? ipO[off-1] : 0.f;
            v[ky*3+1] = okR          ? ipE[off]   : 0.f;
            v[ky*3+2] = okR          ? ipO[off]   : 0.f;
        }
        if (HAS_IN) {
            float s = ssc[ic], sh = ssh[ic];
            #pragma unroll
            for (int ky = 0; ky < 3; ky++) {
                bool okR = (okT || ky > 0);
                v[ky*3+0] = (okR && okL) ? fmaf(v[ky*3+0], s, sh) : 0.f;
                v[ky*3+1] = okR          ? fmaf(v[ky*3+1], s, sh) : 0.f;
                v[ky*3+2] = okR          ? fmaf(v[ky*3+2], s, sh) : 0.f;
            }
        }
        #pragma unroll
        for (int k = 0; k < 9; k++) {
            float t = v[k];
            #pragma unroll
            for (int o = 0; o < OCB; o++)
                acc[o] = fmaf(t, sw[(ic*9+k)*OCB+o], acc[o]);
        }
    }

    // de-interleaved output address
    const size_t oaddr = (ox & 1)*OHALF + oy*(OUTHW/2) + (ox >> 1);
    float ys[OCB];
    #pragma unroll
    for (int o = 0; o < OCB; o++) {
        float y = acc[o];
        y = y >= 0.f ? y : 0.2f*y;
        ys[o] = y;
        out[((size_t)b*OC + ocg*OCB + o)*OUTHW*OUTHW + oaddr] = y;
    }

    // fused stats: block-reduce sum/sumsq per oc, one atomic pair per block
    float s1[OCB], s2[OCB];
    #pragma unroll
    for (int o = 0; o < OCB; o++) { s1[o] = ys[o]; s2[o] = ys[o]*ys[o]; }
    #pragma unroll
    for (int o = 0; o < OCB; o++) {
        #pragma unroll
        for (int off = 16; off; off >>= 1) {
            s1[o] += __shfl_xor_sync(0xffffffffu, s1[o], off);
            s2[o] += __shfl_xor_sync(0xffffffffu, s2[o], off);
        }
    }
    __shared__ float2 red[OCB][8];
    int warp = tid >> 5, lane = tid & 31;
    if (lane == 0) {
        #pragma unroll
        for (int o = 0; o < OCB; o++) red[o][warp] = make_float2(s1[o], s2[o]);
    }
    __syncthreads();
    if (tid < OCB) {
        float a = 0.f, c = 0.f;
        #pragma unroll
        for (int wdx = 0; wdx < 8; wdx++) { a += red[tid][wdx].x; c += red[tid][wdx].y; }
        int bc = b*OC + ocg*OCB + tid;
        atomicAdd(stat_out + bc*2, a);
        atomicAdd(stat_out + bc*2+1, c);
    }
}

// ---------------- conv5 + LeakyReLU + avgpool(2) -> codes (de-interleaved in)
__global__ void __launch_bounds__(256) conv5_pool_k(
                             const float* __restrict__ in, const float* __restrict__ w,
                             const float* __restrict__ bias,
                             const float* __restrict__ stat_in,
                             const float* __restrict__ gamma, const float* __restrict__ beta,
                             float* __restrict__ codes)
{
    const int IC = 128, OCPB = 8;
    const int b = blockIdx.y, ocg = blockIdx.x;
    const int tid = threadIdx.x;
    const int px = tid & 63, osub = tid >> 6;
    const int oy = px >> 3, ox = px & 7;

    __shared__ float sw[IC*9*OCPB];
    __shared__ float ssc[IC], ssh[IC];
    __shared__ float sred[OCPB][64];

    for (int i = tid; i < IC; i += 256) {
        const float invn = 1.f / 256.f;
        float s1 = stat_in[(b*IC+i)*2], s2 = stat_in[(b*IC+i)*2+1];
        float mean = s1 * invn;
        float var  = s2 * invn - mean*mean;
        float sc = gamma[i] * rsqrtf(var + 1e-5f);
        ssc[i] = sc;
        ssh[i] = beta[i] - mean * sc;
    }
    for (int i = tid; i < IC*9*OCPB; i += 256) {
        int o = i % OCPB, t = i / OCPB;
        int k = t % 9, ic = t / 9;
        sw[i] = w[((ocg*OCPB + o)*IC + ic)*9 + k];
    }
    __syncthreads();

    float acc0 = bias[ocg*OCPB + osub*2];
    float acc1 = bias[ocg*OCPB + osub*2 + 1];

    const bool okT = (oy > 0), okL = (ox > 0);
    const float* inb = in + (size_t)b*IC*256 + (2*oy-1)*8 + ox;

    for (int ic = 0; ic < IC; ic++) {
        const float* ipE = inb + ic*256;
        const float* ipO = ipE + 128;
        float s = ssc[ic], sh = ssh[ic];
        float v[9];
        #pragma unroll
        for (int ky = 0; ky < 3; ky++) {
            bool okR = (okT || ky > 0);
            int off = ky*8;
            float l = (okR && okL) ? ipO[off-1] : 0.f;
            float m = okR          ? ipE[off]   : 0.f;
            float r = okR          ? ipO[off]   : 0.f;
            v[ky*3+0] = (okR && okL) ? fmaf(l, s, sh) : 0.f;
            v[ky*3+1] = okR          ? fmaf(m, s, sh) : 0.f;
            v[ky*3+2] = okR          ? fmaf(r, s, sh) : 0.f;
        }
        #pragma unroll
        for (int k = 0; k < 9; k++) {
            float t = v[k];
            acc0 = fmaf(t, sw[(ic*9+k)*OCPB + osub*2],     acc0);
            acc1 = fmaf(t, sw[(ic*9+k)*OCPB + osub*2 + 1], acc1);
        }
    }

    sred[osub*2][px]   = acc0 >= 0.f ? acc0 : 0.2f*acc0;
    sred[osub*2+1][px] = acc1 >= 0.f ? acc1 : 0.2f*acc1;
    __syncthreads();
    if (tid < 32) {
        int o = tid >> 2, q = tid & 3, py = q >> 1, qx = q & 1;
        float s = 0.f;
        #pragma unroll
        for (int yy = 0; yy < 4; yy++)
            #pragma unroll
            for (int xx = 0; xx < 4; xx++)
                s += sred[o][(py*4+yy)*8 + (qx*4+xx)];
        codes[b*512 + (ocg*OCPB + o)*4 + q] = s * (1.f/16.f);
    }
}

// ---------------- LUT weights + AdaInt vertices ------------------------------
__global__ void mlp_k(const float* __restrict__ codes,
                      const float* __restrict__ lw, const float* __restrict__ lb,
                      const float* __restrict__ aw, const float* __restrict__ ab,
                      float* __restrict__ wts, float* __restrict__ verts,
                      float* __restrict__ out_w, float* __restrict__ out_v)
{
    int b = blockIdx.x;
    __shared__ float sc[512];
    __shared__ float pre[96];
    for (int i = threadIdx.x; i < 512; i += blockDim.x) sc[i] = codes[b*512 + i];
    __syncthreads();
    int t = threadIdx.x;
    if (t < 96) {
        float acc = ab[t];
        const float* ar = aw + t*512;
        for (int k = 0; k < 512; k++) acc = fmaf(sc[k], ar[k], acc);
        pre[t] = acc;
    } else if (t < 99) {
        int r = t - 96;
        float acc = lb[r];
        const float* lr = lw + r*512;
        for (int k = 0; k < 512; k++) acc = fmaf(sc[k], lr[k], acc);
        wts[b*3 + r] = acc;
        out_w[b*3 + r] = acc;
    }
    __syncthreads();
    int warp = t >> 5, lane = t & 31;
    if (warp < 3) {
        float x = pre[warp*32 + lane];
        float m = x;
        #pragma unroll
        for (int off = 16; off; off >>= 1) m = fmaxf(m, __shfl_xor_sync(0xffffffffu, m, off));
        float e = expf(x - m);
        float ssum = e;
        #pragma unroll
        for (int off = 16; off; off >>= 1) ssum += __shfl_xor_sync(0xffffffffu, ssum, off);
        float p = e / ssum;
        float cs = p;
        #pragma unroll
        for (int off = 1; off < 32; off <<= 1) {
            float v = __shfl_up_sync(0xffffffffu, cs, off);
            if (lane >= off) cs += v;
        }
        float* vp = verts + (b*3 + warp)*DV;
        float* vo = out_v + (b*3 + warp)*DV;
        if (lane == 0) { vp[0] = 0.f; vo[0] = 0.f; }
        vp[lane+1] = cs;
        vo[lane+1] = cs;
    }
}

// ---------------- lut synthesis into fp16 packed (k,k+1) pairs ---------------
__global__ void lutH_k(const float* __restrict__ bw, const float* __restrict__ wts,
                       uint4* __restrict__ lutH)
{
    int i = blockIdx.x*blockDim.x + threadIdx.x;
    if (i >= B*D3) return;
    int b = i / D3, s = i - b*D3;
    int k = s % DV;
    int s2 = (k < DV-1) ? s+1 : s;
    float w0 = wts[b*3], w1 = wts[b*3+1], w2 = wts[b*3+2];
    float r0, g0, b0, r1, g1, b1;
    {
        const float* p = bw + (size_t)s*3;
        r0 = fmaf(w0, p[0], fmaf(w1, p[1], w2*p[2]));
        p = bw + ((size_t)D3 + s)*3;
        g0 = fmaf(w0, p[0], fmaf(w1, p[1], w2*p[2]));
        p = bw + ((size_t)2*D3 + s)*3;
        b0 = fmaf(w0, p[0], fmaf(w1, p[1], w2*p[2]));
        p = bw + (size_t)s2*3;
        r1 = fmaf(w0, p[0], fmaf(w1, p[1], w2*p[2]));
        p = bw + ((size_t)D3 + s2)*3;
        g1 = fmaf(w0, p[0], fmaf(w1, p[1], w2*p[2]));
        p = bw + ((size_t)2*D3 + s2)*3;
        b1 = fmaf(w0, p[0], fmaf(w1, p[1], w2*p[2]));
    }
    __half2 ha = __floats2half2_rn(r0, g0);
    __half2 hb = __floats2half2_rn(b0, r1);
    __half2 hc = __floats2half2_rn(g1, b1);
    uint4 u;
    u.x = *(unsigned int*)&ha;
    u.y = *(unsigned int*)&hb;
    u.z = *(unsigned int*)&hc;
    u.w = 0u;
    lutH[i] = u;
}

// ---------------- AiLUT transform: inv-table searchsorted + fp16 trilerp -----
__global__ void __launch_bounds__(256) transform_k(
                            const float* __restrict__ lq, const uint4* __restrict__ lutH,
                            const float* __restrict__ verts, float* __restrict__ out)
{
    int b = blockIdx.x >> 10;
    int blk = blockIdx.x & 1023;
    int tid = threadIdx.x;
    __shared__ float sv[3][DV];
    __shared__ int tbl[3][128];
    if (tid < 99) sv[tid/33][tid%33] = verts[b*99 + tid];
    __syncthreads();
    for (int t = tid; t < 384; t += 256) {
        int ch = t >> 7, e = t & 127;
        float edge = (float)e * (1.f/128.f);
        int idx = 0;
        #pragma unroll 8
        for (int m = 1; m <= 32; m++)
            if (sv[ch][m] <= edge) idx = m;
        tbl[ch][e] = idx;
    }
    __syncthreads();

    int n = (blk*256 + tid) * 4;
    const float* lqb = lq + (size_t)b*3*NPIX;
    float4 R  = *(const float4*)(lqb + n);
    float4 G  = *(const float4*)(lqb + NPIX + n);
    float4 Bl = *(const float4*)(lqb + 2*NPIX + n);

    float xr[4] = {R.x, R.y, R.z, R.w};
    float xg[4] = {G.x, G.y, G.z, G.w};
    float xb[4] = {Bl.x, Bl.y, Bl.z, Bl.w};
    float orr[4], org[4], orb[4];

    const uint4* base = lutH + (size_t)b*D3;

    #pragma unroll
    for (int px = 0; px < 4; px++) {
        float crd[3];
        float xs[3] = {xr[px], xg[px], xb[px]};
        #pragma unroll
        for (int ch = 0; ch < 3; ch++) {
            float x = xs[ch];
            int e = min((int)(x * 128.f), 127);
            int idx = tbl[ch][e];
            while (idx < 32 && sv[ch][idx+1] <= x) idx++;
            int lo = min(idx, 31);
            float vl = sv[ch][lo], vh = sv[ch][lo+1];
            float fr = (x - vl) / (vh - vl + 1e-8f);
            float cd = (float)lo + fr;
            crd[ch] = fminf(fmaxf(cd, 0.f), 32.f);
        }
        int i0 = min((int)crd[0], 31);
        int j0 = min((int)crd[1], 31);
        int k0 = min((int)crd[2], 31);
        float fr = crd[0] - (float)i0;
        float fg = crd[1] - (float)j0;
        float fb = crd[2] - (float)k0;

        const uint4* p = base + i0*D2 + j0*DV + k0;
        uint4 c00 = p[0];
        uint4 c01 = p[DV];
        uint4 c10 = p[D2];
        uint4 c11 = p[D2+DV];

        float2 a, bb, c;
        // corner 00
        a  = __half22float2(*(__half2*)&c00.x);   // r0,g0
        bb = __half22float2(*(__half2*)&c00.y);   // b0,r1
        c  = __half22float2(*(__half2*)&c00.z);   // g1,b1
        float l00x = fmaf(fb, bb.y - a.x,  a.x);
        float l00y = fmaf(fb, c.x  - a.y,  a.y);
        float l00z = fmaf(fb, c.y  - bb.x, bb.x);
        // corner 01 (j+1)
        a  = __half22float2(*(__half2*)&c01.x);
        bb = __half22float2(*(__half2*)&c01.y);
        c  = __half22float2(*(__half2*)&c01.z);
        float l01x = fmaf(fb, bb.y - a.x,  a.x);
        float l01y = fmaf(fb, c.x  - a.y,  a.y);
        float l01z = fmaf(fb, c.y  - bb.x, bb.x);
        // corner 10 (i+1)
        a  = __half22float2(*(__half2*)&c10.x);
        bb = __half22float2(*(__half2*)&c10.y);
        c  = __half22float2(*(__half2*)&c10.z);
        float l10x = fmaf(fb, bb.y - a.x,  a.x);
        float l10y = fmaf(fb, c.x  - a.y,  a.y);
        float l10z = fmaf(fb, c.y  - bb.x, bb.x);
        // corner 11
        a  = __half22float2(*(__half2*)&c11.x);
        bb = __half22float2(*(__half2*)&c11.y);
        c  = __half22float2(*(__half2*)&c11.z);
        float l11x = fmaf(fb, bb.y - a.x,  a.x);
        float l11y = fmaf(fb, c.x  - a.y,  a.y);
        float l11z = fmaf(fb, c.y  - bb.x, bb.x);

        float h0x = fmaf(fg, l01x - l00x, l00x);
        float h0y = fmaf(fg, l01y - l00y, l00y);
        float h0z = fmaf(fg, l01z - l00z, l00z);
        float h1x = fmaf(fg, l11x - l10x, l10x);
        float h1y = fmaf(fg, l11y - l10y, l10y);
        float h1z = fmaf(fg, l11z - l10z, l10z);

        orr[px] = fminf(fmaxf(fmaf(fr, h1x - h0x, h0x), 0.f), 1.f);
        org[px] = fminf(fmaxf(fmaf(fr, h1y - h0y, h0y), 0.f), 1.f);
        orb[px] = fminf(fmaxf(fmaf(fr, h1z - h0z, h0z), 0.f), 1.f);
    }

    float* ob = out + (size_t)b*3*NPIX + n;
    *(float4*)(ob)          = make_float4(orr[0], orr[1], orr[2], orr[3]);
    *(float4*)(ob + NPIX)   = make_float4(org[0], org[1], org[2], org[3]);
    *(float4*)(ob + 2*NPIX) = make_float4(orb[0], orb[1], orb[2], orb[3]);
}

// ---------------- host launcher ----------------------------------------------
extern "C" void kernel_launch(void* const* d_in, const int* in_sizes, int n_in,
                              void* d_out, int out_size)
{
    const float* lq  = (const float*)d_in[0];
    const float* w1  = (const float*)d_in[1];
    const float* b1  = (const float*)d_in[2];
    const float* g1  = (const float*)d_in[3];
    const float* be1 = (const float*)d_in[4];
    const float* w2  = (const float*)d_in[5];
    const float* b2  = (const float*)d_in[6];
    const float* g2  = (const float*)d_in[7];
    const float* be2 = (const float*)d_in[8];
    const float* w3  = (const float*)d_in[9];
    const float* b3  = (const float*)d_in[10];
    const float* g3  = (const float*)d_in[11];
    const float* be3 = (const float*)d_in[12];
    const float* w4  = (const float*)d_in[13];
    const float* b4  = (const float*)d_in[14];
    const float* g4  = (const float*)d_in[15];
    const float* be4 = (const float*)d_in[16];
    const float* w5  = (const float*)d_in[17];
    const float* b5  = (const float*)d_in[18];
    const float* lw  = (const float*)d_in[19];
    const float* lb  = (const float*)d_in[20];
    const float* bw  = (const float*)d_in[21];
    const float* aw  = (const float*)d_in[22];
    const float* ab  = (const float*)d_in[23];

    float *res, *x1, *x2, *x3, *x4, *codes, *stats, *wts, *verts;
    uint4* lutH;
    cudaGetSymbolAddress((void**)&res,   g_resized);
    cudaGetSymbolAddress((void**)&x1,    g_x1);
    cudaGetSymbolAddress((void**)&x2,    g_x2);
    cudaGetSymbolAddress((void**)&x3,    g_x3);
    cudaGetSymbolAddress((void**)&x4,    g_x4);
    cudaGetSymbolAddress((void**)&codes, g_codes);
    cudaGetSymbolAddress((void**)&stats, g_stats);
    cudaGetSymbolAddress((void**)&wts,   g_wts);
    cudaGetSymbolAddress((void**)&verts, g_verts);
    cudaGetSymbolAddress((void**)&lutH,  g_lutH);

    float* ss1 = stats;          // 4*16*2  = 128
    float* ss2 = stats + 128;    // 4*32*2  = 256
    float* ss3 = stats + 384;    // 4*64*2  = 512
    float* ss4 = stats + 896;    // 4*128*2 = 1024

    float* out = (float*)d_out;
    const int OFF_W = B*3*NPIX;
    const int OFF_V = OFF_W + B*3;

    zero_k<<<8, 256>>>(stats, 1920);

    resize_k<<<(B*3*256*256 + 255)/256, 256>>>(lq, res);

    conv_k<3, 16, 8, 256, 128, false><<<dim3(64, 2, B), 256>>>(
        res, w1, b1, nullptr, nullptr, nullptr, ss1, x1);

    conv_k<16, 32, 4, 128, 64, true><<<dim3(16, 8, B), 256>>>(
        x1, w2, b2, ss1, g1, be1, ss2, x2);

    conv_k<32, 64, 4, 64, 32, true><<<dim3(4, 16, B), 256>>>(
        x2, w3, b3, ss2, g2, be2, ss3, x3);

    conv_k<64, 128, 4, 32, 16, true><<<dim3(1, 32, B), 256>>>(
        x3, w4, b4, ss3, g3, be3, ss4, x4);

    conv5_pool_k<<<dim3(16, B), 256>>>(x4, w5, b5, ss4, g4, be4, codes);

    mlp_k<<<B, 128>>>(codes, lw, lb, aw, ab, wts, verts, out + OFF_W, out + OFF_V);

    lutH_k<<<(B*D3 + 255)/256, 256>>>(bw, wts, lutH);

    transform_k<<<B*1024, 256>>>(lq, lutH, verts, out);
}